// round 10
// baseline (speedup 1.0000x reference)
#include <cuda_runtime.h>
#include <math.h>

// x[1, 2M, 16] fp32, ~5% NaN. Per-column mean of valid entries; NaNs -> mean.
//
// Single persistent kernel, PER-WARP work stealing (no block syncs in the
// streaming loops):
//   phase1: warps steal 2048-float4 tiles -> per-column sum/count in regs
//   block merge -> global merge -> grid barrier (spin)
//   phase2: warps steal tiles -> reload (__ldcs, L2-hot), NaN->mean,
//           store (__stcs)
// Last finishing block resets all global state (no memset node).

#define C 16
#define THREADS 256
#define TILE 2048LL   // float4s per warp work tile (32 KB)

struct Acc {
    float sum[C];
    float cnt[C];
    unsigned int barrier_ctr;
    unsigned int w1;       // phase-1 warp ticket
    unsigned int w2;       // phase-2 warp ticket
    unsigned int done;     // completion ticket
};
__device__ Acc g_acc;      // static-zeroed; self-reset each run

__global__ void __launch_bounds__(THREADS)
fused_kernel(const float4* __restrict__ in, float4* __restrict__ out,
             long long n4) {
    __shared__ float s_sum[C];
    __shared__ float s_cnt[C];
    __shared__ float s_mean[C];

    const int t    = threadIdx.x;
    const int lane = t & 31;

    if (t < C) { s_sum[t] = 0.0f; s_cnt[t] = 0.0f; }
    __syncthreads();

    const unsigned int n_tiles = (unsigned int)((n4 + TILE - 1) / TILE);
    const int cbase = (lane & 3) * 4;   // TILE multiple of 4 -> fixed per lane

    float ls0 = 0.f, ls1 = 0.f, ls2 = 0.f, ls3 = 0.f;
    float lc0 = 0.f, lc1 = 0.f, lc2 = 0.f, lc3 = 0.f;

    // ---------- phase 1: per-warp work-stealing reduction ----------
    for (;;) {
        unsigned int tile;
        if (lane == 0) tile = atomicAdd(&g_acc.w1, 1u);
        tile = __shfl_sync(0xffffffffu, tile, 0);
        if (tile >= n_tiles) break;

        long long base = (long long)tile * TILE;
        long long end  = base + TILE < n4 ? base + TILE : n4;
        #pragma unroll 4
        for (long long i = base + lane; i < end; i += 32) {
            float4 v = in[i];
            if (v.x == v.x) { ls0 += v.x; lc0 += 1.f; }
            if (v.y == v.y) { ls1 += v.y; lc1 += 1.f; }
            if (v.z == v.z) { ls2 += v.z; lc2 += 1.f; }
            if (v.w == v.w) { ls3 += v.w; lc3 += 1.f; }
        }
    }

    atomicAdd(&s_sum[cbase + 0], ls0);
    atomicAdd(&s_sum[cbase + 1], ls1);
    atomicAdd(&s_sum[cbase + 2], ls2);
    atomicAdd(&s_sum[cbase + 3], ls3);
    atomicAdd(&s_cnt[cbase + 0], lc0);
    atomicAdd(&s_cnt[cbase + 1], lc1);
    atomicAdd(&s_cnt[cbase + 2], lc2);
    atomicAdd(&s_cnt[cbase + 3], lc3);
    __syncthreads();

    if (t < C) {
        atomicAdd(&g_acc.sum[t], s_sum[t]);
        atomicAdd(&g_acc.cnt[t], s_cnt[t]);
        __threadfence();
    }
    __syncthreads();

    // ---------- grid barrier ----------
    if (t == 0) {
        atomicAdd(&g_acc.barrier_ctr, 1u);
        volatile unsigned int* ctr = &g_acc.barrier_ctr;
        while (*ctr < gridDim.x) {
            __nanosleep(64);
        }
        __threadfence();
    }
    __syncthreads();

    if (t < C) {
        s_mean[t] = g_acc.sum[t] / fmaxf(g_acc.cnt[t], 1.0f);
    }
    __syncthreads();

    const float m0 = s_mean[cbase + 0];
    const float m1 = s_mean[cbase + 1];
    const float m2 = s_mean[cbase + 2];
    const float m3 = s_mean[cbase + 3];

    // ---------- phase 2: per-warp work-stealing fill ----------
    for (;;) {
        unsigned int tile;
        if (lane == 0) tile = atomicAdd(&g_acc.w2, 1u);
        tile = __shfl_sync(0xffffffffu, tile, 0);
        if (tile >= n_tiles) break;

        long long base = (long long)tile * TILE;
        long long end  = base + TILE < n4 ? base + TILE : n4;
        #pragma unroll 4
        for (long long i = base + lane; i < end; i += 32) {
            float4 v = __ldcs(&in[i]);
            if (!(v.x == v.x)) v.x = m0;
            if (!(v.y == v.y)) v.y = m1;
            if (!(v.z == v.z)) v.z = m2;
            if (!(v.w == v.w)) v.w = m3;
            __stcs(&out[i], v);
        }
    }

    // ---------- self-reset by last block ----------
    __syncthreads();
    if (t == 0) {
        __threadfence();
        unsigned int ticket = atomicAdd(&g_acc.done, 1u);
        if (ticket == gridDim.x - 1) {
            #pragma unroll
            for (int c = 0; c < C; c++) { g_acc.sum[c] = 0.0f; g_acc.cnt[c] = 0.0f; }
            g_acc.barrier_ctr = 0u;
            g_acc.w1 = 0u;
            g_acc.w2 = 0u;
            g_acc.done = 0u;
            __threadfence();
        }
    }
}

extern "C" void kernel_launch(void* const* d_in, const int* in_sizes, int n_in,
                              void* d_out, int out_size) {
    const float4* in = (const float4*)d_in[0];
    float4* out      = (float4*)d_out;
    long long n  = (long long)in_sizes[0];
    long long n4 = n / 4;

    static int grid = 0;
    if (grid == 0) {
        int sm_count = 0;
        cudaDeviceGetAttribute(&sm_count, cudaDevAttrMultiProcessorCount, 0);
        int blocks_per_sm = 0;
        cudaOccupancyMaxActiveBlocksPerMultiprocessor(
            &blocks_per_sm, fused_kernel, THREADS, 0);
        if (blocks_per_sm < 1) blocks_per_sm = 1;
        grid = sm_count * blocks_per_sm;
    }

    fused_kernel<<<grid, THREADS>>>(in, out, n4);
}

// round 12
// speedup vs baseline: 1.3030x; 1.3030x over previous
#include <cuda_runtime.h>
#include <math.h>

// x[1, 2M, 16] fp32, ~5% NaN. Per-column mean of valid entries; NaNs -> mean.
// R7 static two-phase structure + occupancy/MLP fix:
//   - __launch_bounds__(256, 8): 8 blocks/SM (2048 thr/SM, occ -> ~100%)
//   - unroll 8: 8 outstanding LDG.128 per thread
//   - phase2 reverse order + __ldcs/__stcs (L2 retention, proven in R7)
//   - self-reset of global state by last block (no memset node, proven R9)

#define C 16
#define THREADS 256

struct Acc {
    float sum[C];
    float cnt[C];
    unsigned int barrier_ctr;
    unsigned int done;
};
__device__ Acc g_acc;   // static-zeroed; self-reset each run

__global__ void __launch_bounds__(THREADS, 8)
fused_kernel(const float4* __restrict__ in, float4* __restrict__ out,
             long long n4, long long chunk) {
    __shared__ float s_sum[C];
    __shared__ float s_cnt[C];
    __shared__ float s_mean[C];

    const int t = threadIdx.x;
    if (t < C) { s_sum[t] = 0.0f; s_cnt[t] = 0.0f; }
    __syncthreads();

    const long long base  = (long long)blockIdx.x * chunk;
    const long long end   = (base + chunk < n4) ? (base + chunk) : n4;
    const long long start = base + t;

    const int cbase = ((int)(start & 3)) * 4;   // loop-invariant column group

    float ls0 = 0.f, ls1 = 0.f, ls2 = 0.f, ls3 = 0.f;
    float lc0 = 0.f, lc1 = 0.f, lc2 = 0.f, lc3 = 0.f;

    // ---------- phase 1: reduce own tile, deep unroll for MLP ----------
    #pragma unroll 8
    for (long long i = start; i < end; i += THREADS) {
        float4 v = in[i];
        if (v.x == v.x) { ls0 += v.x; lc0 += 1.f; }
        if (v.y == v.y) { ls1 += v.y; lc1 += 1.f; }
        if (v.z == v.z) { ls2 += v.z; lc2 += 1.f; }
        if (v.w == v.w) { ls3 += v.w; lc3 += 1.f; }
    }

    atomicAdd(&s_sum[cbase + 0], ls0);
    atomicAdd(&s_sum[cbase + 1], ls1);
    atomicAdd(&s_sum[cbase + 2], ls2);
    atomicAdd(&s_sum[cbase + 3], ls3);
    atomicAdd(&s_cnt[cbase + 0], lc0);
    atomicAdd(&s_cnt[cbase + 1], lc1);
    atomicAdd(&s_cnt[cbase + 2], lc2);
    atomicAdd(&s_cnt[cbase + 3], lc3);
    __syncthreads();

    if (t < C) {
        atomicAdd(&g_acc.sum[t], s_sum[t]);
        atomicAdd(&g_acc.cnt[t], s_cnt[t]);
        __threadfence();
    }
    __syncthreads();

    // ---------- grid barrier ----------
    if (t == 0) {
        atomicAdd(&g_acc.barrier_ctr, 1u);
        volatile unsigned int* ctr = &g_acc.barrier_ctr;
        while (*ctr < gridDim.x) {
            __nanosleep(64);
        }
        __threadfence();
    }
    __syncthreads();

    if (t < C) {
        s_mean[t] = g_acc.sum[t] / fmaxf(g_acc.cnt[t], 1.0f);
    }
    __syncthreads();

    const float m0 = s_mean[cbase + 0];
    const float m1 = s_mean[cbase + 1];
    const float m2 = s_mean[cbase + 2];
    const float m3 = s_mean[cbase + 3];

    // ---------- phase 2: reverse-order fill (L2-hot input first) ----------
    if (start < end) {
        long long K = (end - start + THREADS - 1) / THREADS;
        #pragma unroll 8
        for (long long k = K - 1; k >= 0; k--) {
            long long i = start + k * THREADS;
            float4 v = __ldcs(&in[i]);
            if (!(v.x == v.x)) v.x = m0;
            if (!(v.y == v.y)) v.y = m1;
            if (!(v.z == v.z)) v.z = m2;
            if (!(v.w == v.w)) v.w = m3;
            __stcs(&out[i], v);
        }
    }

    // ---------- self-reset by last block ----------
    __syncthreads();
    if (t == 0) {
        __threadfence();
        unsigned int ticket = atomicAdd(&g_acc.done, 1u);
        if (ticket == gridDim.x - 1) {
            #pragma unroll
            for (int c = 0; c < C; c++) { g_acc.sum[c] = 0.0f; g_acc.cnt[c] = 0.0f; }
            g_acc.barrier_ctr = 0u;
            g_acc.done = 0u;
            __threadfence();
        }
    }
}

extern "C" void kernel_launch(void* const* d_in, const int* in_sizes, int n_in,
                              void* d_out, int out_size) {
    const float4* in = (const float4*)d_in[0];
    float4* out      = (float4*)d_out;
    long long n  = (long long)in_sizes[0];
    long long n4 = n / 4;

    static int grid = 0;
    if (grid == 0) {
        int sm_count = 0;
        cudaDeviceGetAttribute(&sm_count, cudaDevAttrMultiProcessorCount, 0);
        int blocks_per_sm = 0;
        cudaOccupancyMaxActiveBlocksPerMultiprocessor(
            &blocks_per_sm, fused_kernel, THREADS, 0);
        if (blocks_per_sm < 1) blocks_per_sm = 1;
        grid = sm_count * blocks_per_sm;
    }

    long long chunk = (n4 + grid - 1) / grid;

    fused_kernel<<<grid, THREADS>>>(in, out, n4, chunk);
}